// round 5
// baseline (speedup 1.0000x reference)
#include <cuda_runtime.h>
#include <cuda_bf16.h>
#include <cstdint>

#define BATCH 4
#define NQ    4096
#define NK    4096
#define DIM   256
#define SCALE 0.17677669529663687f   // (256/8)^-0.5

#define BM 64
#define BN 64
#define NBLK (NK / BN)
#define THREADS 256

#define QK_STRIDE 264   // 256 + 8 pad (bf16) -> 528B rows, conflict-free LDSM, 16B-mult
#define P_STRIDE  72    // 64 + 8 pad

// device-global scratch (no allocations allowed)
__device__ __nv_bfloat16 g_Qn[BATCH * NQ * DIM];
__device__ __nv_bfloat16 g_Kn[BATCH * NK * DIM];
__device__ __nv_bfloat16 g_Vb[BATCH * NK * DIM];
__device__ float         g_Vsum[BATCH * DIM];

// smem layout (bytes)
#define TILE_B (BN * QK_STRIDE * 2)          // 33792
#define SQ_OFF  0u
#define SK0_OFF (TILE_B)
#define SK1_OFF (2u * TILE_B)
#define SV0_OFF (3u * TILE_B)
#define SV1_OFF (4u * TILE_B)
#define SP_OFF  (5u * TILE_B)                // P: 64 x 72 bf16 = 9216
#define SL_OFF  (5u * TILE_B + 9216u)        // float[2][64]
#define SVS_OFF (5u * TILE_B + 9728u)        // float[256]
static const int SMEM_BYTES = 5 * TILE_B + 9216 + 512 + 1024 + 256;

// ---------------------------------------------------------------- helpers
__device__ __forceinline__ uint32_t smem_u32(const void* p) {
    return (uint32_t)__cvta_generic_to_shared(p);
}

#define LDSM_X4(r0, r1, r2, r3, addr)                                              \
    asm volatile("ldmatrix.sync.aligned.m8n8.x4.shared.b16 {%0,%1,%2,%3},[%4];"    \
                 : "=r"(r0), "=r"(r1), "=r"(r2), "=r"(r3) : "r"(addr))

#define LDSM_X4_T(r0, r1, r2, r3, addr)                                                 \
    asm volatile("ldmatrix.sync.aligned.m8n8.x4.trans.shared.b16 {%0,%1,%2,%3},[%4];"   \
                 : "=r"(r0), "=r"(r1), "=r"(r2), "=r"(r3) : "r"(addr))

#define MMA16816(d, a0, a1, a2, a3, b0, b1)                                        \
    asm volatile("mma.sync.aligned.m16n8k16.row.col.f32.bf16.bf16.f32 "            \
                 "{%0,%1,%2,%3},{%4,%5,%6,%7},{%8,%9},{%0,%1,%2,%3};"              \
                 : "+f"(d[0]), "+f"(d[1]), "+f"(d[2]), "+f"(d[3])                  \
                 : "r"(a0), "r"(a1), "r"(a2), "r"(a3), "r"(b0), "r"(b1))

__device__ __forceinline__ void cp16(uint32_t s, const void* g) {
    asm volatile("cp.async.cg.shared.global [%0], [%1], 16;" :: "r"(s), "l"(g));
}
#define CP_COMMIT() asm volatile("cp.async.commit_group;" ::: "memory")
#define CP_WAIT(n)  asm volatile("cp.async.wait_group %0;" :: "n"(n) : "memory")

// ---------------------------------------------------------------- prep kernels
__global__ void zero_vsum_kernel() { g_Vsum[threadIdx.x] = 0.0f; }

__global__ void vprep_kernel(const float* __restrict__ v) {
    int b = blockIdx.y, chunk = blockIdx.x, d = threadIdx.x;
    size_t base = ((size_t)b * NK + (size_t)chunk * 128) * DIM + d;
    float sum = 0.0f;
    for (int r = 0; r < 128; r++) {
        float x = v[base + (size_t)r * DIM];
        sum += x;
        g_Vb[base + (size_t)r * DIM] = __float2bfloat16(x);
    }
    atomicAdd(&g_Vsum[b * DIM + d], sum);
}

__global__ void normalize_kernel(const float* __restrict__ q, const float* __restrict__ k) {
    int gw = (blockIdx.x * blockDim.x + threadIdx.x) >> 5;
    int lane = threadIdx.x & 31;
    const float* src;
    __nv_bfloat16* dst;
    int row;
    if (gw < BATCH * NQ) { src = q; dst = g_Qn; row = gw; }
    else                 { src = k; dst = g_Kn; row = gw - BATCH * NQ; }

    const float4* p = (const float4*)(src + (size_t)row * DIM);
    float4 v0 = p[lane];
    float4 v1 = p[lane + 32];
    float ss = v0.x * v0.x + v0.y * v0.y + v0.z * v0.z + v0.w * v0.w
             + v1.x * v1.x + v1.y * v1.y + v1.z * v1.z + v1.w * v1.w;
#pragma unroll
    for (int off = 16; off > 0; off >>= 1) ss += __shfl_xor_sync(0xffffffffu, ss, off);
    float sc = 1.0f / fmaxf(sqrtf(ss), 1e-12f);

    __nv_bfloat162* drow = (__nv_bfloat162*)(dst + (size_t)row * DIM);
    drow[lane * 2 + 0]      = __floats2bfloat162_rn(v0.x * sc, v0.y * sc);
    drow[lane * 2 + 1]      = __floats2bfloat162_rn(v0.z * sc, v0.w * sc);
    drow[64 + lane * 2 + 0] = __floats2bfloat162_rn(v1.x * sc, v1.y * sc);
    drow[64 + lane * 2 + 1] = __floats2bfloat162_rn(v1.z * sc, v1.w * sc);
}

// ---------------------------------------------------------------- fused attention
// out = (Vsum + sum_j (exp(s_j)-1) v_j) / (NK + sum_j (exp(s_j)-1)),  |s| <= SCALE.
extern "C" __global__ void __launch_bounds__(THREADS, 1)
flash_kernel(float* __restrict__ out) {
    extern __shared__ __align__(128) char smem[];
    const uint32_t sb = smem_u32(smem);
    const int b  = blockIdx.y;
    const int q0 = blockIdx.x * BM;
    const int tid = threadIdx.x, lane = tid & 31, wid = tid >> 5;
    const int wm = wid & 3;    // QK: 4 warps along M (16 rows each)
    const int wn = wid >> 2;   // QK: 2 warps along keys (32 each)
    const int wvm = wid >> 2;  // PV: 2 warps along M (32 rows each)
    const int wvn = wid & 3;   // PV: 4 warps along N (64 cols each)

    __nv_bfloat16* sQ = (__nv_bfloat16*)(smem + SQ_OFF);
    __nv_bfloat16* sP = (__nv_bfloat16*)(smem + SP_OFF);
    float* sL2 = (float*)(smem + SL_OFF);     // [2][64]
    float* sVS = (float*)(smem + SVS_OFF);

    // ---- load Q tile ----
    const uint4* gq = (const uint4*)(g_Qn + ((size_t)(b * NQ + q0)) * DIM);
    for (int i = tid; i < BM * 32; i += THREADS) {
        int r = i >> 5, c = i & 31;
        *(uint4*)(sQ + r * QK_STRIDE + c * 8) = gq[i];
    }
    if (tid < DIM) sVS[tid] = g_Vsum[b * DIM + tid];

    const char* gK = (const char*)(g_Kn + (size_t)b * NK * DIM);
    const char* gV = (const char*)(g_Vb + (size_t)b * NK * DIM);

    // prefetch block 0 (other smem region; safe before barrier)
    for (int i = tid; i < 4096; i += THREADS) {
        int r = (i >> 5) & 63, c = i & 31;
        if (i < 2048) cp16(sb + SK0_OFF + r * 528 + c * 16, gK + r * 512 + c * 16);
        else          cp16(sb + SV0_OFF + r * 528 + c * 16, gV + r * 512 + c * 16);
    }
    CP_COMMIT();
    __syncthreads();   // Q visible

    // Q fragments register-resident for all blocks
    uint32_t qf[16][4];
    {
        const uint32_t aQ = sb + SQ_OFF +
            ((wm * 16 + (lane & 15)) * QK_STRIDE + (lane >> 4) * 8) * 2;
#pragma unroll
        for (int ks = 0; ks < 16; ks++)
            LDSM_X4(qf[ks][0], qf[ks][1], qf[ks][2], qf[ks][3], aQ + ks * 32);
    }

    float oAcc[16][4];
#pragma unroll
    for (int a = 0; a < 16; a++)
#pragma unroll
        for (int j = 0; j < 4; j++) oAcc[a][j] = 0.0f;

    const int g = lane >> 3;
    const uint32_t bKrel = (uint32_t)(((wn * 32 + (g >> 1) * 8 + (lane & 7)) * QK_STRIDE
                                       + (g & 1) * 8) * 2);
    const uint32_t aP = sb + SP_OFF +
        ((wvm * 32 + (lane & 15)) * P_STRIDE + (lane >> 4) * 8) * 2;
    const uint32_t bVrel = (uint32_t)((((g & 1) * 8 + (lane & 7)) * QK_STRIDE
                                      + wvn * 64 + (g >> 1) * 8) * 2);

    float regLo = 0.0f, regHi = 0.0f;

    for (int kb = 0; kb < NBLK; kb++) {
        const uint32_t skb = (kb & 1) ? SK1_OFF : SK0_OFF;
        const uint32_t svb = (kb & 1) ? SV1_OFF : SV0_OFF;

        CP_WAIT(0);        // buffer kb landed
        __syncthreads();   // + all warps done with PV(kb-1) (read other buffer)

        // now safe to overwrite the other buffer
        if (kb + 1 < NBLK) {
            const uint32_t skn = (kb & 1) ? SK0_OFF : SK1_OFF;
            const uint32_t svn = (kb & 1) ? SV0_OFF : SV1_OFF;
            const char* gKn = gK + (size_t)(kb + 1) * BN * 512;
            const char* gVn = gV + (size_t)(kb + 1) * BN * 512;
            for (int i = tid; i < 4096; i += THREADS) {
                int r = (i >> 5) & 63, c = i & 31;
                if (i < 2048) cp16(sb + skn + r * 528 + c * 16, gKn + r * 512 + c * 16);
                else          cp16(sb + svn + r * 528 + c * 16, gVn + r * 512 + c * 16);
            }
            CP_COMMIT();
        }

        // ---- S = Q @ K^T (warp tile 16 x 32), software-pipelined K LDSM ----
        float sAcc[4][4];
#pragma unroll
        for (int a = 0; a < 4; a++)
#pragma unroll
            for (int j = 0; j < 4; j++) sAcc[a][j] = 0.0f;

        const uint32_t bK0 = sb + skb + bKrel;
        const uint32_t bK1 = bK0 + 16 * QK_STRIDE * 2;
        uint32_t kfA[8], kfB[8];
        LDSM_X4(kfA[0], kfA[1], kfA[2], kfA[3], bK0);
        LDSM_X4(kfA[4], kfA[5], kfA[6], kfA[7], bK1);
#pragma unroll
        for (int ks = 0; ks < 16; ks++) {
            uint32_t* cur = (ks & 1) ? kfB : kfA;
            uint32_t* nxt = (ks & 1) ? kfA : kfB;
            if (ks < 15) {
                LDSM_X4(nxt[0], nxt[1], nxt[2], nxt[3], bK0 + (ks + 1) * 32);
                LDSM_X4(nxt[4], nxt[5], nxt[6], nxt[7], bK1 + (ks + 1) * 32);
            }
            MMA16816(sAcc[0], qf[ks][0], qf[ks][1], qf[ks][2], qf[ks][3], cur[0], cur[1]);
            MMA16816(sAcc[1], qf[ks][0], qf[ks][1], qf[ks][2], qf[ks][3], cur[2], cur[3]);
            MMA16816(sAcc[2], qf[ks][0], qf[ks][1], qf[ks][2], qf[ks][3], cur[4], cur[5]);
            MMA16816(sAcc[3], qf[ks][0], qf[ks][1], qf[ks][2], qf[ks][3], cur[6], cur[7]);
        }

        // ---- e = exp(s*SCALE)-1; accumulate partial row sums in regs; P -> smem ----
#pragma unroll
        for (int a = 0; a < 4; a++) {
#pragma unroll
            for (int j = 0; j < 4; j++)
                sAcc[a][j] = __expf(sAcc[a][j] * SCALE) - 1.0f;
            regLo += sAcc[a][0] + sAcc[a][1];
            regHi += sAcc[a][2] + sAcc[a][3];
        }
        {
            int prow = wm * 16 + (lane >> 2);
            int pcol = wn * 32 + 2 * (lane & 3);
#pragma unroll
            for (int a = 0; a < 4; a++) {
                *(__nv_bfloat162*)(sP + prow * P_STRIDE + pcol + a * 8) =
                    __floats2bfloat162_rn(sAcc[a][0], sAcc[a][1]);
                *(__nv_bfloat162*)(sP + (prow + 8) * P_STRIDE + pcol + a * 8) =
                    __floats2bfloat162_rn(sAcc[a][2], sAcc[a][3]);
            }
        }
        __syncthreads();   // P visible

        // ---- O += P @ V (warp tile 32 rows x 64 cols), pipelined P/V LDSM ----
        const uint32_t bV = sb + svb + bVrel;
        uint32_t pf[2][8], vf[2][4];
        LDSM_X4(pf[0][0], pf[0][1], pf[0][2], pf[0][3], aP);
        LDSM_X4(pf[0][4], pf[0][5], pf[0][6], pf[0][7], aP + 16 * P_STRIDE * 2);
        LDSM_X4_T(vf[0][0], vf[0][1], vf[0][2], vf[0][3], bV);
#pragma unroll
        for (int ks = 0; ks < 4; ks++) {
            const int pt = ks & 1;
#pragma unroll
            for (int pr = 0; pr < 4; pr++) {
                const int idx = ks * 4 + pr;
                const int vt = idx & 1;
                if (pr < 3) {
                    LDSM_X4_T(vf[vt ^ 1][0], vf[vt ^ 1][1], vf[vt ^ 1][2], vf[vt ^ 1][3],
                              bV + ks * (16 * QK_STRIDE * 2) + (pr + 1) * 32);
                } else if (ks < 3) {
                    LDSM_X4_T(vf[vt ^ 1][0], vf[vt ^ 1][1], vf[vt ^ 1][2], vf[vt ^ 1][3],
                              bV + (ks + 1) * (16 * QK_STRIDE * 2));
                    LDSM_X4(pf[pt ^ 1][0], pf[pt ^ 1][1], pf[pt ^ 1][2], pf[pt ^ 1][3],
                            aP + (ks + 1) * 32);
                    LDSM_X4(pf[pt ^ 1][4], pf[pt ^ 1][5], pf[pt ^ 1][6], pf[pt ^ 1][7],
                            aP + 16 * P_STRIDE * 2 + (ks + 1) * 32);
                }
                MMA16816(oAcc[pr * 2],
                         pf[pt][0], pf[pt][1], pf[pt][2], pf[pt][3], vf[vt][0], vf[vt][1]);
                MMA16816(oAcc[pr * 2 + 1],
                         pf[pt][0], pf[pt][1], pf[pt][2], pf[pt][3], vf[vt][2], vf[vt][3]);
                MMA16816(oAcc[8 + pr * 2],
                         pf[pt][4], pf[pt][5], pf[pt][6], pf[pt][7], vf[vt][0], vf[vt][1]);
                MMA16816(oAcc[8 + pr * 2 + 1],
                         pf[pt][4], pf[pt][5], pf[pt][6], pf[pt][7], vf[vt][2], vf[vt][3]);
            }
        }
    }

    // ---- finalize row sums (one reduce at the end) ----
    {
        float lo = regLo, hi = regHi;
        lo += __shfl_xor_sync(0xffffffffu, lo, 1);
        lo += __shfl_xor_sync(0xffffffffu, lo, 2);
        hi += __shfl_xor_sync(0xffffffffu, hi, 1);
        hi += __shfl_xor_sync(0xffffffffu, hi, 2);
        if ((lane & 3) == 0) {
            sL2[wn * 64 + wm * 16 + (lane >> 2)] = lo;
            sL2[wn * 64 + wm * 16 + 8 + (lane >> 2)] = hi;
        }
    }
    __syncthreads();

    // ---- writeout ----
    float* op = out + ((size_t)(b * NQ + q0)) * DIM;
#pragma unroll
    for (int mi = 0; mi < 2; mi++) {
        const int r1 = wvm * 32 + mi * 16 + (lane >> 2);
        const float inv1 = 1.0f / ((float)NK + sL2[r1] + sL2[64 + r1]);
        const float inv2 = 1.0f / ((float)NK + sL2[r1 + 8] + sL2[64 + r1 + 8]);
#pragma unroll
        for (int a = 0; a < 8; a++) {
            int c = wvn * 64 + a * 8 + 2 * (lane & 3);
            float vs0 = sVS[c], vs1 = sVS[c + 1];
            float* acc = oAcc[mi * 8 + a];
            float2 w1 = make_float2((vs0 + acc[0]) * inv1, (vs1 + acc[1]) * inv1);
            float2 w2 = make_float2((vs0 + acc[2]) * inv2, (vs1 + acc[3]) * inv2);
            *(float2*)(op + (size_t)r1 * DIM + c) = w1;
            *(float2*)(op + (size_t)(r1 + 8) * DIM + c) = w2;
        }
    }
}

// ---------------------------------------------------------------- launch
extern "C" void kernel_launch(void* const* d_in, const int* in_sizes, int n_in,
                              void* d_out, int out_size) {
    const float* q = (const float*)d_in[0];
    const float* k = (const float*)d_in[1];
    const float* v = (const float*)d_in[2];
    float* out = (float*)d_out;

    cudaFuncSetAttribute(flash_kernel, cudaFuncAttributeMaxDynamicSharedMemorySize, SMEM_BYTES);

    zero_vsum_kernel<<<1, BATCH * DIM>>>();
    vprep_kernel<<<dim3(NK / 128, BATCH), 256>>>(v);
    normalize_kernel<<<(2 * BATCH * NQ) / 8, 256>>>(q, k);
    flash_kernel<<<dim3(NQ / BM, BATCH), THREADS, SMEM_BYTES>>>(out);
}

// round 6
// speedup vs baseline: 1.2336x; 1.2336x over previous
#include <cuda_runtime.h>
#include <cuda_bf16.h>
#include <cstdint>

#define BATCH 4
#define NQ    4096
#define NK    4096
#define DIM   256
#define SCALE 0.17677669529663687f   // (256/8)^-0.5

#define BM 128
#define BN 64
#define NBLK (NK / BN)
#define THREADS 256

#define QK_STRIDE 264   // 256 + 8 pad (bf16) -> 528B rows, conflict-free LDSM, 16B-mult

// device-global scratch (no allocations allowed)
__device__ __nv_bfloat16 g_Qn[BATCH * NQ * DIM];
__device__ __nv_bfloat16 g_Kn[BATCH * NK * DIM];
__device__ __nv_bfloat16 g_Vb[BATCH * NK * DIM];
__device__ float         g_Vsum[BATCH * DIM];

// smem layout (bytes)
#define KV_TILE_B (BN * QK_STRIDE * 2)        // 33792
#define SQ_OFF  0u                            // Q 128 x 264 bf16 = 67584
#define SK0_OFF 67584u
#define SV0_OFF 101376u
#define SK1_OFF 135168u
#define SV1_OFF 168960u
#define SVS_OFF 202752u                       // float[256]
static const int SMEM_BYTES = 203776;

// ---------------------------------------------------------------- helpers
__device__ __forceinline__ uint32_t smem_u32(const void* p) {
    return (uint32_t)__cvta_generic_to_shared(p);
}

#define LDSM_X4(r0, r1, r2, r3, addr)                                              \
    asm volatile("ldmatrix.sync.aligned.m8n8.x4.shared.b16 {%0,%1,%2,%3},[%4];"    \
                 : "=r"(r0), "=r"(r1), "=r"(r2), "=r"(r3) : "r"(addr))

#define LDSM_X4_T(r0, r1, r2, r3, addr)                                                 \
    asm volatile("ldmatrix.sync.aligned.m8n8.x4.trans.shared.b16 {%0,%1,%2,%3},[%4];"   \
                 : "=r"(r0), "=r"(r1), "=r"(r2), "=r"(r3) : "r"(addr))

#define MMA16816(d, a0, a1, a2, a3, b0, b1)                                        \
    asm volatile("mma.sync.aligned.m16n8k16.row.col.f32.bf16.bf16.f32 "            \
                 "{%0,%1,%2,%3},{%4,%5,%6,%7},{%8,%9},{%0,%1,%2,%3};"              \
                 : "+f"(d[0]), "+f"(d[1]), "+f"(d[2]), "+f"(d[3])                  \
                 : "r"(a0), "r"(a1), "r"(a2), "r"(a3), "r"(b0), "r"(b1))

__device__ __forceinline__ void cp16(uint32_t s, const void* g) {
    asm volatile("cp.async.cg.shared.global [%0], [%1], 16;" :: "r"(s), "l"(g));
}
#define CP_COMMIT() asm volatile("cp.async.commit_group;" ::: "memory")
#define CP_WAIT(n)  asm volatile("cp.async.wait_group %0;" :: "n"(n) : "memory")

// ---------------------------------------------------------------- prep kernels
__global__ void zero_vsum_kernel() { g_Vsum[threadIdx.x] = 0.0f; }

__global__ void vprep_kernel(const float* __restrict__ v) {
    int b = blockIdx.y, chunk = blockIdx.x, d = threadIdx.x;
    size_t base = ((size_t)b * NK + (size_t)chunk * 128) * DIM + d;
    float sum = 0.0f;
    for (int r = 0; r < 128; r++) {
        float x = v[base + (size_t)r * DIM];
        sum += x;
        g_Vb[base + (size_t)r * DIM] = __float2bfloat16(x);
    }
    atomicAdd(&g_Vsum[b * DIM + d], sum);
}

__global__ void normalize_kernel(const float* __restrict__ q, const float* __restrict__ k) {
    int gw = (blockIdx.x * blockDim.x + threadIdx.x) >> 5;
    int lane = threadIdx.x & 31;
    const float* src;
    __nv_bfloat16* dst;
    int row;
    if (gw < BATCH * NQ) { src = q; dst = g_Qn; row = gw; }
    else                 { src = k; dst = g_Kn; row = gw - BATCH * NQ; }

    const float4* p = (const float4*)(src + (size_t)row * DIM);
    float4 v0 = p[lane];
    float4 v1 = p[lane + 32];
    float ss = v0.x * v0.x + v0.y * v0.y + v0.z * v0.z + v0.w * v0.w
             + v1.x * v1.x + v1.y * v1.y + v1.z * v1.z + v1.w * v1.w;
#pragma unroll
    for (int off = 16; off > 0; off >>= 1) ss += __shfl_xor_sync(0xffffffffu, ss, off);
    float sc = 1.0f / fmaxf(sqrtf(ss), 1e-12f);

    __nv_bfloat162* drow = (__nv_bfloat162*)(dst + (size_t)row * DIM);
    drow[lane * 2 + 0]      = __floats2bfloat162_rn(v0.x * sc, v0.y * sc);
    drow[lane * 2 + 1]      = __floats2bfloat162_rn(v0.z * sc, v0.w * sc);
    drow[64 + lane * 2 + 0] = __floats2bfloat162_rn(v1.x * sc, v1.y * sc);
    drow[64 + lane * 2 + 1] = __floats2bfloat162_rn(v1.z * sc, v1.w * sc);
}

// ---------------------------------------------------------------- fused attention
// out = (Vsum + sum_j (exp(s_j)-1) v_j) / (NK + sum_j (exp(s_j)-1)),  |s| <= SCALE.
// Each warp owns 16 query rows end-to-end: P stays in registers (C-layout == A-layout),
// no inter-warp exchange, single barrier per key block (buffer swap).
extern "C" __global__ void __launch_bounds__(THREADS, 1)
flash_kernel(float* __restrict__ out) {
    extern __shared__ __align__(128) char smem[];
    const uint32_t sb = smem_u32(smem);
    const int b  = blockIdx.y;
    const int q0 = blockIdx.x * BM;
    const int tid = threadIdx.x, lane = tid & 31, wid = tid >> 5;
    const int g = lane >> 3;

    float* sVS = (float*)(smem + SVS_OFF);

    // ---- load Q tile (plain LDG->STS; covered by first barrier) ----
    const uint4* gq = (const uint4*)(g_Qn + ((size_t)(b * NQ + q0)) * DIM);
    __nv_bfloat16* sQ = (__nv_bfloat16*)(smem + SQ_OFF);
    for (int i = tid; i < BM * 32; i += THREADS) {
        int r = i >> 5, c = i & 31;
        *(uint4*)(sQ + r * QK_STRIDE + c * 8) = gq[i];
    }
    if (tid < DIM) sVS[tid] = g_Vsum[b * DIM + tid];

    const char* gK = (const char*)(g_Kn + (size_t)b * NK * DIM);
    const char* gV = (const char*)(g_Vb + (size_t)b * NK * DIM);

    // prefetch block 0
    for (int i = tid; i < 4096; i += THREADS) {
        int r = (i >> 5) & 63, c = i & 31;
        if (i < 2048) cp16(sb + SK0_OFF + r * 528 + c * 16, gK + r * 512 + c * 16);
        else          cp16(sb + SV0_OFF + r * 528 + c * 16, gV + r * 512 + c * 16);
    }
    CP_COMMIT();

    // per-warp addresses
    const uint32_t aQ = sb + SQ_OFF +
        (uint32_t)(((wid * 16 + (lane & 15)) * QK_STRIDE + (lane >> 4) * 8) * 2);
    const uint32_t bKrel = (uint32_t)((((g >> 1) * 8 + (lane & 7)) * QK_STRIDE
                                      + (g & 1) * 8) * 2);
    const uint32_t bVrel = (uint32_t)((((g & 1) * 8 + (lane & 7)) * QK_STRIDE
                                      + (g >> 1) * 8) * 2);

    float oAcc[32][4];
#pragma unroll
    for (int a = 0; a < 32; a++)
#pragma unroll
        for (int j = 0; j < 4; j++) oAcc[a][j] = 0.0f;

    float eLo = 0.0f, eHi = 0.0f;   // row-sum partials (rows lane>>2, +8)

    for (int kb = 0; kb < NBLK; kb++) {
        const uint32_t skb = (kb & 1) ? SK1_OFF : SK0_OFF;
        const uint32_t svb = (kb & 1) ? SV1_OFF : SV0_OFF;

        CP_WAIT(0);        // buffer kb landed
        __syncthreads();   // all warps done reading the other buffer (PV of kb-1)

        if (kb + 1 < NBLK) {
            const uint32_t skn = (kb & 1) ? SK0_OFF : SK1_OFF;
            const uint32_t svn = (kb & 1) ? SV0_OFF : SV1_OFF;
            const char* gKn = gK + (size_t)(kb + 1) * BN * 512;
            const char* gVn = gV + (size_t)(kb + 1) * BN * 512;
            for (int i = tid; i < 4096; i += THREADS) {
                int r = (i >> 5) & 63, c = i & 31;
                if (i < 2048) cp16(sb + skn + r * 528 + c * 16, gKn + r * 512 + c * 16);
                else          cp16(sb + svn + r * 528 + c * 16, gVn + r * 512 + c * 16);
            }
            CP_COMMIT();
        }

        // ---- S = Q @ K^T : warp tile 16 rows x 64 keys ----
        float sAcc[8][4];
#pragma unroll
        for (int a = 0; a < 8; a++)
#pragma unroll
            for (int j = 0; j < 4; j++) sAcc[a][j] = 0.0f;

        const uint32_t bK = sb + skb + bKrel;
#pragma unroll
        for (int ks = 0; ks < 16; ks++) {
            uint32_t a0, a1, a2, a3;
            LDSM_X4(a0, a1, a2, a3, aQ + ks * 32);
#pragma unroll
            for (int kt = 0; kt < 4; kt++) {
                uint32_t b0, b1, b2, b3;
                LDSM_X4(b0, b1, b2, b3, bK + kt * (16 * QK_STRIDE * 2) + ks * 32);
                MMA16816(sAcc[2 * kt],     a0, a1, a2, a3, b0, b1);
                MMA16816(sAcc[2 * kt + 1], a0, a1, a2, a3, b2, b3);
            }
        }

        // ---- e = exp(s*SCALE)-1; row-sum partials; pack P in registers ----
        uint32_t pA[4][4];
#pragma unroll
        for (int a = 0; a < 8; a++) {
#pragma unroll
            for (int j = 0; j < 4; j++)
                sAcc[a][j] = __expf(sAcc[a][j] * SCALE) - 1.0f;
            eLo += sAcc[a][0] + sAcc[a][1];
            eHi += sAcc[a][2] + sAcc[a][3];
        }
#pragma unroll
        for (int kg = 0; kg < 4; kg++) {
            __nv_bfloat162 t0 = __floats2bfloat162_rn(sAcc[2 * kg][0], sAcc[2 * kg][1]);
            __nv_bfloat162 t1 = __floats2bfloat162_rn(sAcc[2 * kg][2], sAcc[2 * kg][3]);
            __nv_bfloat162 t2 = __floats2bfloat162_rn(sAcc[2 * kg + 1][0], sAcc[2 * kg + 1][1]);
            __nv_bfloat162 t3 = __floats2bfloat162_rn(sAcc[2 * kg + 1][2], sAcc[2 * kg + 1][3]);
            pA[kg][0] = *(uint32_t*)&t0;
            pA[kg][1] = *(uint32_t*)&t1;
            pA[kg][2] = *(uint32_t*)&t2;
            pA[kg][3] = *(uint32_t*)&t3;
        }

        // ---- O += P @ V : warp tile 16 rows x 256 cols ----
        const uint32_t bV = sb + svb + bVrel;
#pragma unroll
        for (int ks = 0; ks < 4; ks++) {
            const uint32_t vb = bV + ks * (16 * QK_STRIDE * 2);
#pragma unroll
            for (int cg = 0; cg < 4; cg++) {
#pragma unroll
                for (int pr = 0; pr < 4; pr++) {
                    uint32_t v0, v1, v2, v3;
                    LDSM_X4_T(v0, v1, v2, v3, vb + cg * 128 + pr * 32);
                    const int idx = cg * 8 + pr * 2;
                    MMA16816(oAcc[idx],     pA[ks][0], pA[ks][1], pA[ks][2], pA[ks][3], v0, v1);
                    MMA16816(oAcc[idx + 1], pA[ks][0], pA[ks][1], pA[ks][2], pA[ks][3], v2, v3);
                }
            }
        }
    }

    // ---- finalize row sums (warp-local quad reduce) ----
    eLo += __shfl_xor_sync(0xffffffffu, eLo, 1);
    eLo += __shfl_xor_sync(0xffffffffu, eLo, 2);
    eHi += __shfl_xor_sync(0xffffffffu, eHi, 1);
    eHi += __shfl_xor_sync(0xffffffffu, eHi, 2);
    const float inv1 = 1.0f / ((float)NK + eLo);
    const float inv2 = 1.0f / ((float)NK + eHi);

    // ---- writeout ----
    const int r1 = wid * 16 + (lane >> 2);
    float* op = out + ((size_t)(b * NQ + q0 + r1)) * DIM;
#pragma unroll
    for (int cg = 0; cg < 4; cg++) {
#pragma unroll
        for (int pr = 0; pr < 4; pr++) {
#pragma unroll
            for (int h = 0; h < 2; h++) {
                const int idx = cg * 8 + pr * 2 + h;
                const int c = cg * 64 + pr * 16 + h * 8 + 2 * (lane & 3);
                float vs0 = sVS[c], vs1 = sVS[c + 1];
                float* acc = oAcc[idx];
                *(float2*)(op + c) =
                    make_float2((vs0 + acc[0]) * inv1, (vs1 + acc[1]) * inv1);
                *(float2*)(op + 8 * DIM + c) =
                    make_float2((vs0 + acc[2]) * inv2, (vs1 + acc[3]) * inv2);
            }
        }
    }
}

// ---------------------------------------------------------------- launch
extern "C" void kernel_launch(void* const* d_in, const int* in_sizes, int n_in,
                              void* d_out, int out_size) {
    const float* q = (const float*)d_in[0];
    const float* k = (const float*)d_in[1];
    const float* v = (const float*)d_in[2];
    float* out = (float*)d_out;

    cudaFuncSetAttribute(flash_kernel, cudaFuncAttributeMaxDynamicSharedMemorySize, SMEM_BYTES);

    zero_vsum_kernel<<<1, BATCH * DIM>>>();
    vprep_kernel<<<dim3(NK / 128, BATCH), 256>>>(v);
    normalize_kernel<<<(2 * BATCH * NQ) / 8, 256>>>(q, k);
    flash_kernel<<<dim3(NQ / BM, BATCH), THREADS, SMEM_BYTES>>>(out);
}